// round 1
// baseline (speedup 1.0000x reference)
#include <cuda_runtime.h>
#include <cuda_bf16.h>
#include <math.h>

// Problem constants
#define BATCH   2
#define SEQ     2048
#define DM      2048
#define NH      16
#define KVH     4
#define HD      128
#define QKV_N   3072      // 2048 + 2*512
#define BS      (BATCH*SEQ)   // 4096
#define QSCALE  0.08838834764831845f  // 1/sqrt(128)

// ---------------------------------------------------------------------------
// Scratch (static __device__ arrays; no allocation allowed)
// ---------------------------------------------------------------------------
__device__ float g_xn  [BS * DM];                    // rmsnorm1 output
__device__ float g_qkv [BS * QKV_N];                 // qkv projection (clipped)
__device__ float g_q   [BATCH * NH  * SEQ * HD];     // [b,h,s,d], pre-scaled
__device__ float g_k   [BATCH * KVH * SEQ * HD];     // [b,kvh,s,d]
__device__ float g_v   [BATCH * KVH * SEQ * HD];
__device__ float g_attn[BS * DM];                    // attention out, [b,s,h*d]

// ---------------------------------------------------------------------------
// RMSNorm: one block per row of 2048
// ---------------------------------------------------------------------------
__global__ void rmsnorm_kernel(const float* __restrict__ x,
                               const float* __restrict__ w,
                               float* __restrict__ y)
{
    __shared__ float red[256];
    int row = blockIdx.x;
    const float4* xr = (const float4*)(x + (size_t)row * DM);
    float s = 0.f;
    #pragma unroll
    for (int i = threadIdx.x; i < DM/4; i += 256) {
        float4 v = xr[i];
        s += v.x*v.x + v.y*v.y + v.z*v.z + v.w*v.w;
    }
    red[threadIdx.x] = s;
    __syncthreads();
    for (int st = 128; st > 0; st >>= 1) {
        if (threadIdx.x < st) red[threadIdx.x] += red[threadIdx.x + st];
        __syncthreads();
    }
    float rs = rsqrtf(red[0] * (1.0f/(float)DM) + 1e-5f);
    float4* yr = (float4*)(y + (size_t)row * DM);
    const float4* wr = (const float4*)w;
    #pragma unroll
    for (int i = threadIdx.x; i < DM/4; i += 256) {
        float4 v = xr[i];
        float4 ww = wr[i];
        v.x = v.x * rs * ww.x;
        v.y = v.y * rs * ww.y;
        v.z = v.z * rs * ww.z;
        v.w = v.w * rs * ww.w;
        yr[i] = v;
    }
}

// ---------------------------------------------------------------------------
// SGEMM: C[M,N] = A[M,K] @ B[K,N], 128x128x16 tiles, 8x8 microtile, 256 thr.
// EPI 0: clip to [-8,8]   EPI 1: add Resid, write C
// ---------------------------------------------------------------------------
template<int EPI>
__global__ void __launch_bounds__(256, 2)
sgemm_kernel(const float* __restrict__ A, const float* __restrict__ B,
             const float* __restrict__ Resid, float* __restrict__ C,
             int M, int N, int K)
{
    __shared__ float As[16 * 132];
    __shared__ float Bs[16 * 132];

    int tid = threadIdx.x;
    int ty = tid >> 4;        // 0..15
    int tx = tid & 15;        // 0..15
    int rowBase = blockIdx.y * 128;
    int colBase = blockIdx.x * 128;

    float acc[8][8];
    #pragma unroll
    for (int i = 0; i < 8; i++)
        #pragma unroll
        for (int j = 0; j < 8; j++) acc[i][j] = 0.f;

    for (int k0 = 0; k0 < K; k0 += 16) {
        // Load A tile (128x16) transposed into As[16][132]
        #pragma unroll
        for (int t = 0; t < 2; t++) {
            int idx = tid + t * 256;          // float4 id 0..511
            int r  = idx >> 2;                // 0..127
            int c4 = idx & 3;                 // 0..3
            float4 a = *(const float4*)&A[(size_t)(rowBase + r) * K + k0 + c4*4];
            As[(c4*4+0)*132 + r] = a.x;
            As[(c4*4+1)*132 + r] = a.y;
            As[(c4*4+2)*132 + r] = a.z;
            As[(c4*4+3)*132 + r] = a.w;
        }
        // Load B tile (16x128) into Bs[16][132]
        #pragma unroll
        for (int t = 0; t < 2; t++) {
            int idx = tid + t * 256;
            int kk = idx >> 5;                // 0..15
            int c4 = idx & 31;                // 0..31
            *(float4*)&Bs[kk*132 + c4*4] =
                *(const float4*)&B[(size_t)(k0 + kk) * N + colBase + c4*4];
        }
        __syncthreads();

        #pragma unroll
        for (int kk = 0; kk < 16; kk++) {
            float a[8], b[8];
            *(float4*)&a[0] = *(float4*)&As[kk*132 + ty*8];
            *(float4*)&a[4] = *(float4*)&As[kk*132 + ty*8 + 4];
            *(float4*)&b[0] = *(float4*)&Bs[kk*132 + tx*8];
            *(float4*)&b[4] = *(float4*)&Bs[kk*132 + tx*8 + 4];
            #pragma unroll
            for (int i = 0; i < 8; i++)
                #pragma unroll
                for (int j = 0; j < 8; j++)
                    acc[i][j] += a[i] * b[j];
        }
        __syncthreads();
    }

    // Epilogue
    #pragma unroll
    for (int i = 0; i < 8; i++) {
        int r = rowBase + ty*8 + i;
        #pragma unroll
        for (int j4 = 0; j4 < 2; j4++) {
            int c = colBase + tx*8 + j4*4;
            float4 v;
            v.x = acc[i][j4*4+0];
            v.y = acc[i][j4*4+1];
            v.z = acc[i][j4*4+2];
            v.w = acc[i][j4*4+3];
            if (EPI == 0) {
                v.x = fminf(8.f, fmaxf(-8.f, v.x));
                v.y = fminf(8.f, fmaxf(-8.f, v.y));
                v.z = fminf(8.f, fmaxf(-8.f, v.z));
                v.w = fminf(8.f, fmaxf(-8.f, v.w));
            } else {
                float4 rv = *(const float4*)&Resid[(size_t)r * N + c];
                v.x += rv.x; v.y += rv.y; v.z += rv.z; v.w += rv.w;
            }
            *(float4*)&C[(size_t)r * N + c] = v;
        }
    }
}

// ---------------------------------------------------------------------------
// RoPE + split: reads g_qkv rows, writes g_q (scaled), g_k, g_v
// one block per (b,s)
// ---------------------------------------------------------------------------
__global__ void rope_kernel(const float* __restrict__ qkv,
                            const int* __restrict__ posids,
                            const float* __restrict__ rsin,
                            const float* __restrict__ rcos,
                            float* __restrict__ Qo,
                            float* __restrict__ Ko,
                            float* __restrict__ Vo)
{
    int bs = blockIdx.x;              // 0..4095
    int b = bs >> 11;
    int s = bs & 2047;
    int pos = posids[bs];
    const float* base = qkv + (size_t)bs * QKV_N;

    for (int idx = threadIdx.x; idx < QKV_N; idx += 256) {
        int head = idx >> 7;
        int d = idx & 127;
        float x = base[idx];
        if (head < NH + KVH) {  // q or k -> rope
            float c  = rcos[pos * HD + d];
            float sn = rsin[pos * HD + d];
            float other = (d < 64) ? -base[head*HD + d + 64]
                                   :  base[head*HD + d - 64];
            float val = x * c + other * sn;
            if (head < NH) {
                Qo[(((size_t)(b*NH + head)) * SEQ + s) * HD + d] = val * QSCALE;
            } else {
                Ko[(((size_t)(b*KVH + head - NH)) * SEQ + s) * HD + d] = val;
            }
        } else {
            Vo[(((size_t)(b*KVH + head - NH - KVH)) * SEQ + s) * HD + d] = x;
        }
    }
}

// ---------------------------------------------------------------------------
// Flash attention (causal, GQA): BM=64 q rows, BN=64 k cols, 256 threads.
// Q pre-scaled. Out written as [b, s, h, d] -> contiguous [BS, 2048].
// ---------------------------------------------------------------------------
__global__ void __launch_bounds__(256, 1)
attn_kernel(const float* __restrict__ Q, const float* __restrict__ K,
            const float* __restrict__ V, const int* __restrict__ amask,
            float* __restrict__ Out)
{
    extern __shared__ float sm[];
    float* Qs = sm;                     // [64][129]
    float* Ks = Qs + 64*129;            // [64][129]
    float* Vs = Ks + 64*129;            // [64][128]
    float* Ss = Vs + 64*128;            // [64][65]
    float* mS  = Ss + 64*65;            // [64]
    float* lS  = mS + 64;               // [64]
    float* scS = lS + 64;               // [64]
    float* mk  = scS + 64;              // [64] mask bias

    int tid = threadIdx.x;
    int qt = blockIdx.x;                // 0..31
    int h  = blockIdx.y;                // 0..15
    int b  = blockIdx.z;                // 0..1
    int kvh = h >> 2;

    const float* Qg = Q + ((size_t)(b*NH + h) * SEQ + qt*64) * HD;
    const float* Kg = K + ((size_t)(b*KVH + kvh) * SEQ) * HD;
    const float* Vg = V + ((size_t)(b*KVH + kvh) * SEQ) * HD;

    // Load Q tile
    for (int i = tid; i < 64*128; i += 256) {
        int r = i >> 7, d = i & 127;
        Qs[r*129 + d] = Qg[(size_t)r*HD + d];
    }
    if (tid < 64) { mS[tid] = -1e30f; lS[tid] = 0.f; }

    float o[32];
    #pragma unroll
    for (int j = 0; j < 32; j++) o[j] = 0.f;

    int orow = tid & 63;
    int od   = (tid >> 6) * 32;
    int tr = tid >> 4, tc = tid & 15;

    for (int kt = 0; kt <= qt; kt++) {
        __syncthreads();   // prior O-update (reads Ss/Vs) done before overwrite
        for (int i = tid; i < 64*128; i += 256) {
            int r = i >> 7, d = i & 127;
            Ks[r*129 + d] = Kg[(size_t)(kt*64 + r)*HD + d];
            Vs[r*128 + d] = Vg[(size_t)(kt*64 + r)*HD + d];
        }
        if (tid < 64)
            mk[tid] = (amask[b*SEQ + kt*64 + tid] > 0) ? 0.f : -1e30f;
        __syncthreads();

        // S = Q @ K^T  (64x64), 4x4 per thread
        float acc[4][4];
        #pragma unroll
        for (int i = 0; i < 4; i++)
            #pragma unroll
            for (int j = 0; j < 4; j++) acc[i][j] = 0.f;

        #pragma unroll 4
        for (int kk = 0; kk < 128; kk++) {
            float a0 = Qs[(tr*4+0)*129 + kk];
            float a1 = Qs[(tr*4+1)*129 + kk];
            float a2 = Qs[(tr*4+2)*129 + kk];
            float a3 = Qs[(tr*4+3)*129 + kk];
            float b0 = Ks[(tc*4+0)*129 + kk];
            float b1 = Ks[(tc*4+1)*129 + kk];
            float b2 = Ks[(tc*4+2)*129 + kk];
            float b3 = Ks[(tc*4+3)*129 + kk];
            acc[0][0] += a0*b0; acc[0][1] += a0*b1; acc[0][2] += a0*b2; acc[0][3] += a0*b3;
            acc[1][0] += a1*b0; acc[1][1] += a1*b1; acc[1][2] += a1*b2; acc[1][3] += a1*b3;
            acc[2][0] += a2*b0; acc[2][1] += a2*b1; acc[2][2] += a2*b2; acc[2][3] += a2*b3;
            acc[3][0] += a3*b0; acc[3][1] += a3*b1; acc[3][2] += a3*b2; acc[3][3] += a3*b3;
        }

        int rg0 = qt*64 + tr*4;
        int cg0 = kt*64 + tc*4;
        #pragma unroll
        for (int i = 0; i < 4; i++)
            #pragma unroll
            for (int j = 0; j < 4; j++) {
                float v = acc[i][j] + mk[tc*4 + j];
                if (cg0 + j > rg0 + i) v = -1e30f;   // causal
                Ss[(tr*4+i)*65 + tc*4 + j] = v;
            }
        __syncthreads();

        // Online softmax per row (threads 0..63)
        if (tid < 64) {
            int r = tid;
            float mo = mS[r];
            float mx = mo;
            #pragma unroll 8
            for (int c = 0; c < 64; c++) mx = fmaxf(mx, Ss[r*65 + c]);
            float sc = __expf(mo - mx);
            float l = lS[r] * sc;
            #pragma unroll 8
            for (int c = 0; c < 64; c++) {
                float p = __expf(Ss[r*65 + c] - mx);
                Ss[r*65 + c] = p;
                l += p;
            }
            mS[r] = mx; lS[r] = l; scS[r] = sc;
        }
        __syncthreads();

        // O update: each thread owns 1 row x 32 dims
        float sc = scS[orow];
        #pragma unroll
        for (int j = 0; j < 32; j++) o[j] *= sc;
        #pragma unroll 2
        for (int k = 0; k < 64; k++) {
            float p = Ss[orow*65 + k];
            const float4* vr = (const float4*)&Vs[k*128 + od];
            #pragma unroll
            for (int j4 = 0; j4 < 8; j4++) {
                float4 v = vr[j4];
                o[j4*4+0] += p*v.x;
                o[j4*4+1] += p*v.y;
                o[j4*4+2] += p*v.z;
                o[j4*4+3] += p*v.w;
            }
        }
    }

    float inv = 1.f / lS[orow];
    int row = qt*64 + orow;
    float* og = Out + (((size_t)(b*SEQ + row)) * NH + h) * HD + od;
    #pragma unroll
    for (int j4 = 0; j4 < 8; j4++) {
        float4 v;
        v.x = o[j4*4+0] * inv;
        v.y = o[j4*4+1] * inv;
        v.z = o[j4*4+2] * inv;
        v.w = o[j4*4+3] * inv;
        *(float4*)&og[j4*4] = v;
    }
}

// ---------------------------------------------------------------------------
// kernel_launch
// ---------------------------------------------------------------------------
extern "C" void kernel_launch(void* const* d_in, const int* in_sizes, int n_in,
                              void* d_out, int out_size)
{
    const float* hidden = (const float*)d_in[0];
    const int*   amask  = (const int*)  d_in[1];
    const int*   posids = (const int*)  d_in[2];
    const float* wqkv   = (const float*)d_in[3];
    const float* w_out  = (const float*)d_in[4];
    const float* n1w    = (const float*)d_in[5];
    const float* n2w    = (const float*)d_in[6];
    const float* rsin   = (const float*)d_in[7];
    const float* rcos   = (const float*)d_in[8];
    float* out = (float*)d_out;

    float *p_xn, *p_qkv, *p_q, *p_k, *p_v, *p_attn;
    cudaGetSymbolAddress((void**)&p_xn,   g_xn);
    cudaGetSymbolAddress((void**)&p_qkv,  g_qkv);
    cudaGetSymbolAddress((void**)&p_q,    g_q);
    cudaGetSymbolAddress((void**)&p_k,    g_k);
    cudaGetSymbolAddress((void**)&p_v,    g_v);
    cudaGetSymbolAddress((void**)&p_attn, g_attn);

    // 1. pre-norm
    rmsnorm_kernel<<<BS, 256>>>(hidden, n1w, p_xn);

    // 2. QKV projection + clip
    {
        dim3 grid(QKV_N/128, BS/128);
        sgemm_kernel<0><<<grid, 256>>>(p_xn, wqkv, nullptr, p_qkv, BS, QKV_N, DM);
    }

    // 3. RoPE + split
    rope_kernel<<<BS, 256>>>(p_qkv, posids, rsin, rcos, p_q, p_k, p_v);

    // 4. flash attention
    {
        int smem = (64*129*2 + 64*128 + 64*65 + 64*4) * sizeof(float); // 116480
        cudaFuncSetAttribute(attn_kernel,
                             cudaFuncAttributeMaxDynamicSharedMemorySize, smem);
        dim3 grid(SEQ/64, NH, BATCH);
        attn_kernel<<<grid, 256, smem>>>(p_q, p_k, p_v, amask, p_attn);
    }

    // 5. out-proj + residual add -> out[0 : BS*DM]
    {
        dim3 grid(DM/128, BS/128);
        sgemm_kernel<1><<<grid, 256>>>(p_attn, w_out, hidden, out, BS, DM, DM);
    }

    // 6. post-norm -> out[BS*DM : 2*BS*DM]
    rmsnorm_kernel<<<BS, 256>>>(out, n2w, out + (size_t)BS * DM);
}

// round 3
// speedup vs baseline: 1.4836x; 1.4836x over previous
#include <cuda_runtime.h>
#include <cuda_bf16.h>
#include <math.h>
#include <stdint.h>

// Problem constants
#define BATCH   2
#define SEQ     2048
#define DM      2048
#define NH      16
#define KVH     4
#define HD      128
#define QKV_N   3072
#define BS      (BATCH*SEQ)   // 4096
#define QSCALE  0.08838834764831845f

// ---------------------------------------------------------------------------
// Scratch
// ---------------------------------------------------------------------------
__device__ float g_qkv [BS * QKV_N];
__device__ float g_q   [BATCH * NH  * SEQ * HD];
__device__ float g_k   [BATCH * KVH * SEQ * HD];
__device__ float g_v   [BATCH * KVH * SEQ * HD];
__device__ float g_attn[BS * DM];

__device__ __nv_bfloat16 g_xn_h [BS * DM];
__device__ __nv_bfloat16 g_xn_l [BS * DM];
__device__ __nv_bfloat16 g_at_h [BS * DM];
__device__ __nv_bfloat16 g_at_l [BS * DM];
__device__ __nv_bfloat16 g_wq_h [DM * QKV_N];
__device__ __nv_bfloat16 g_wq_l [DM * QKV_N];
__device__ __nv_bfloat16 g_wo_h [DM * DM];
__device__ __nv_bfloat16 g_wo_l [DM * DM];

// ---------------------------------------------------------------------------
// PTX helpers (compute_103-safe: mma.sync / ldmatrix / cp.async only)
// ---------------------------------------------------------------------------
__device__ __forceinline__ uint32_t smem_u32(const void* p) {
    uint32_t a;
    asm("{ .reg .u64 t; cvta.to.shared.u64 t, %1; cvt.u32.u64 %0, t; }"
        : "=r"(a) : "l"(p));
    return a;
}
__device__ __forceinline__ void cp16(uint32_t dst, const void* src) {
    asm volatile("cp.async.cg.shared.global [%0], [%1], 16;"
                 :: "r"(dst), "l"(src));
}
__device__ __forceinline__ void cp_commit() {
    asm volatile("cp.async.commit_group;" ::: "memory");
}
template<int N>
__device__ __forceinline__ void cp_wait() {
    asm volatile("cp.async.wait_group %0;" :: "n"(N) : "memory");
}
__device__ __forceinline__ void ldsm_x4(uint32_t* r, uint32_t addr) {
    asm volatile("ldmatrix.sync.aligned.m8n8.x4.shared.b16 {%0,%1,%2,%3}, [%4];"
                 : "=r"(r[0]), "=r"(r[1]), "=r"(r[2]), "=r"(r[3]) : "r"(addr));
}
__device__ __forceinline__ void ldsm_x4t(uint32_t* r, uint32_t addr) {
    asm volatile("ldmatrix.sync.aligned.m8n8.x4.trans.shared.b16 {%0,%1,%2,%3}, [%4];"
                 : "=r"(r[0]), "=r"(r[1]), "=r"(r[2]), "=r"(r[3]) : "r"(addr));
}
__device__ __forceinline__ void mma_bf16(float* d, const uint32_t* a, const uint32_t* b) {
    asm volatile(
        "mma.sync.aligned.m16n8k16.row.col.f32.bf16.bf16.f32 "
        "{%0,%1,%2,%3}, {%4,%5,%6,%7}, {%8,%9}, {%0,%1,%2,%3};"
        : "+f"(d[0]), "+f"(d[1]), "+f"(d[2]), "+f"(d[3])
        : "r"(a[0]), "r"(a[1]), "r"(a[2]), "r"(a[3]), "r"(b[0]), "r"(b[1]));
}

// ---------------------------------------------------------------------------
// RMSNorm (fp32 out)
// ---------------------------------------------------------------------------
__global__ void rmsnorm_kernel(const float* __restrict__ x,
                               const float* __restrict__ w,
                               float* __restrict__ y)
{
    __shared__ float red[256];
    int row = blockIdx.x;
    const float4* xr = (const float4*)(x + (size_t)row * DM);
    float s = 0.f;
    #pragma unroll
    for (int i = threadIdx.x; i < DM/4; i += 256) {
        float4 v = xr[i];
        s += v.x*v.x + v.y*v.y + v.z*v.z + v.w*v.w;
    }
    red[threadIdx.x] = s;
    __syncthreads();
    for (int st = 128; st > 0; st >>= 1) {
        if (threadIdx.x < st) red[threadIdx.x] += red[threadIdx.x + st];
        __syncthreads();
    }
    float rs = rsqrtf(red[0] * (1.0f/(float)DM) + 1e-5f);
    float4* yr = (float4*)(y + (size_t)row * DM);
    const float4* wr = (const float4*)w;
    #pragma unroll
    for (int i = threadIdx.x; i < DM/4; i += 256) {
        float4 v = xr[i];
        float4 ww = wr[i];
        v.x = v.x * rs * ww.x;
        v.y = v.y * rs * ww.y;
        v.z = v.z * rs * ww.z;
        v.w = v.w * rs * ww.w;
        yr[i] = v;
    }
}

// RMSNorm -> bf16 hi/lo split output
__global__ void rmsnorm_split_kernel(const float* __restrict__ x,
                                     const float* __restrict__ w,
                                     __nv_bfloat16* __restrict__ yh,
                                     __nv_bfloat16* __restrict__ yl)
{
    __shared__ float red[256];
    int row = blockIdx.x;
    const float4* xr = (const float4*)(x + (size_t)row * DM);
    float s = 0.f;
    #pragma unroll
    for (int i = threadIdx.x; i < DM/4; i += 256) {
        float4 v = xr[i];
        s += v.x*v.x + v.y*v.y + v.z*v.z + v.w*v.w;
    }
    red[threadIdx.x] = s;
    __syncthreads();
    for (int st = 128; st > 0; st >>= 1) {
        if (threadIdx.x < st) red[threadIdx.x] += red[threadIdx.x + st];
        __syncthreads();
    }
    float rs = rsqrtf(red[0] * (1.0f/(float)DM) + 1e-5f);
    const float4* wr = (const float4*)w;
    #pragma unroll
    for (int i = threadIdx.x; i < DM/4; i += 256) {
        float4 v = xr[i];
        float4 ww = wr[i];
        float f[4] = {v.x*rs*ww.x, v.y*rs*ww.y, v.z*rs*ww.z, v.w*rs*ww.w};
        __nv_bfloat16 h[4], l[4];
        #pragma unroll
        for (int j = 0; j < 4; j++) {
            h[j] = __float2bfloat16(f[j]);
            l[j] = __float2bfloat16(f[j] - __bfloat162float(h[j]));
        }
        size_t o = (size_t)row * DM + i*4;
        *(ulonglong1*)&yh[o] = *(ulonglong1*)h;
        *(ulonglong1*)&yl[o] = *(ulonglong1*)l;
    }
}

// fp32 -> bf16 hi/lo split (grid-strided)
__global__ void split_kernel(const float* __restrict__ x,
                             __nv_bfloat16* __restrict__ xh,
                             __nv_bfloat16* __restrict__ xl, int n4)
{
    int i = blockIdx.x * blockDim.x + threadIdx.x;
    if (i >= n4) return;
    float4 v = ((const float4*)x)[i];
    float f[4] = {v.x, v.y, v.z, v.w};
    __nv_bfloat16 h[4], l[4];
    #pragma unroll
    for (int j = 0; j < 4; j++) {
        h[j] = __float2bfloat16(f[j]);
        l[j] = __float2bfloat16(f[j] - __bfloat162float(h[j]));
    }
    *(ulonglong1*)&xh[(size_t)i*4] = *(ulonglong1*)h;
    *(ulonglong1*)&xl[(size_t)i*4] = *(ulonglong1*)l;
}

// ---------------------------------------------------------------------------
// HMMA GEMM, bfx3: C = (Ah+Al)@(Bh+Bl) ~= Ah@Bh + Ah@Bl + Al@Bh
// CTA 128x128, k-chunk 32, 8 warps (warp tile 64x32), cp.async double buffer.
// EPI 0: clip [-8,8].  EPI 1: +Resid.
// ---------------------------------------------------------------------------
#define A_STRIDE  80        // 64B data + 16B pad
#define B_STRIDE  272       // 256B data + 16B pad
#define AH_OFF    0
#define AL_OFF    10240     // 128*80
#define B_OFF     20480
#define BH_OFF    (B_OFF)
#define BL_OFF    (B_OFF + 8704)   // 32*272
#define CHUNK_SZ  37888     // 20480 + 2*8704
#define HG_SMEM   (2*CHUNK_SZ)

template<int EPI>
__global__ void __launch_bounds__(256)
hgemm_kernel(const __nv_bfloat16* __restrict__ Ah, const __nv_bfloat16* __restrict__ Al,
             const __nv_bfloat16* __restrict__ Bh, const __nv_bfloat16* __restrict__ Bl,
             const float* __restrict__ Resid, float* __restrict__ C,
             int M, int N, int K)
{
    extern __shared__ char sm[];
    uint32_t sb = smem_u32(sm);

    int tid  = threadIdx.x;
    int lane = tid & 31;
    int warp = tid >> 5;
    int warpM = warp & 1;       // 0..1 -> m offset *64
    int warpN = warp >> 1;      // 0..3 -> n offset *32
    int rowBase = blockIdx.y * 128;
    int colBase = blockIdx.x * 128;

    float acc[4][4][4];   // [mt][n8][4]
    #pragma unroll
    for (int i = 0; i < 4; i++)
        #pragma unroll
        for (int j = 0; j < 4; j++)
            #pragma unroll
            for (int q = 0; q < 4; q++) acc[i][j][q] = 0.f;

    int nC = K / 32;

    // tile loader
    auto issue = [&](int c) {
        int buf = c & 1;
        uint32_t base = sb + buf * CHUNK_SZ;
        int k0 = c * 32;
        // A: 2 vars x 512 cp.async (128 rows x 4 x16B)
        #pragma unroll
        for (int it = 0; it < 2; it++) {
            int idx = it * 256 + tid;          // 0..511
            int r  = idx >> 2;
            int kc = idx & 3;
            size_t go = (size_t)(rowBase + r) * K + k0 + kc*8;
            uint32_t so = r * A_STRIDE + kc * 16;
            cp16(base + AH_OFF + so, Ah + go);
            cp16(base + AL_OFF + so, Al + go);
        }
        // B: 2 vars x 512 cp.async (32 rows x 16 x16B)
        #pragma unroll
        for (int it = 0; it < 2; it++) {
            int idx = it * 256 + tid;
            int r   = idx >> 4;
            int c16 = idx & 15;
            size_t go = (size_t)(k0 + r) * N + colBase + c16*8;
            uint32_t so = r * B_STRIDE + c16 * 16;
            cp16(base + BH_OFF + so, Bh + go);
            cp16(base + BL_OFF + so, Bl + go);
        }
        cp_commit();
    };

    issue(0);

    for (int c = 0; c < nC; c++) {
        if (c + 1 < nC) { issue(c + 1); cp_wait<1>(); }
        else            { cp_wait<0>(); }
        __syncthreads();

        uint32_t base = sb + (c & 1) * CHUNK_SZ;

        #pragma unroll
        for (int kk = 0; kk < 2; kk++) {
            uint32_t aR[2][4][4];
            #pragma unroll
            for (int mt = 0; mt < 4; mt++) {
                int r = warpM*64 + mt*16 + (lane & 15);
                uint32_t col = ((lane >> 4) * 16) + kk * 32;
                ldsm_x4(aR[0][mt], base + AH_OFF + r*A_STRIDE + col);
                ldsm_x4(aR[1][mt], base + AL_OFF + r*A_STRIDE + col);
            }
            uint32_t bR[2][2][4];
            #pragma unroll
            for (int nt = 0; nt < 2; nt++) {
                int r = kk*16 + (lane & 15);
                uint32_t col = (uint32_t)(warpN*32 + nt*16) * 2 + ((lane >> 4) * 16);
                ldsm_x4t(bR[0][nt], base + BH_OFF + r*B_STRIDE + col);
                ldsm_x4t(bR[1][nt], base + BL_OFF + r*B_STRIDE + col);
            }
            #pragma unroll
            for (int mt = 0; mt < 4; mt++) {
                #pragma unroll
                for (int n8 = 0; n8 < 4; n8++) {
                    int nt = n8 >> 1, hf = (n8 & 1) * 2;
                    mma_bf16(acc[mt][n8], aR[0][mt], &bR[0][nt][hf]);   // hh
                    mma_bf16(acc[mt][n8], aR[0][mt], &bR[1][nt][hf]);   // hl
                    mma_bf16(acc[mt][n8], aR[1][mt], &bR[0][nt][hf]);   // lh
                }
            }
        }
        __syncthreads();
    }

    // Epilogue
    int rg = lane >> 2;
    int cg = (lane & 3) * 2;
    #pragma unroll
    for (int mt = 0; mt < 4; mt++) {
        #pragma unroll
        for (int n8 = 0; n8 < 4; n8++) {
            int r0 = rowBase + warpM*64 + mt*16 + rg;
            int cc = colBase + warpN*32 + n8*8 + cg;
            #pragma unroll
            for (int half = 0; half < 2; half++) {
                int r = r0 + half * 8;
                float2 v;
                v.x = acc[mt][n8][half*2+0];
                v.y = acc[mt][n8][half*2+1];
                if (EPI == 0) {
                    v.x = fminf(8.f, fmaxf(-8.f, v.x));
                    v.y = fminf(8.f, fmaxf(-8.f, v.y));
                } else {
                    float2 rv = *(const float2*)&Resid[(size_t)r * N + cc];
                    v.x += rv.x; v.y += rv.y;
                }
                *(float2*)&C[(size_t)r * N + cc] = v;
            }
        }
    }
}

// ---------------------------------------------------------------------------
// RoPE + split
// ---------------------------------------------------------------------------
__global__ void rope_kernel(const float* __restrict__ qkv,
                            const int* __restrict__ posids,
                            const float* __restrict__ rsin,
                            const float* __restrict__ rcos,
                            float* __restrict__ Qo,
                            float* __restrict__ Ko,
                            float* __restrict__ Vo)
{
    int bs = blockIdx.x;
    int b = bs >> 11;
    int s = bs & 2047;
    int pos = posids[bs];
    const float* base = qkv + (size_t)bs * QKV_N;

    for (int idx = threadIdx.x; idx < QKV_N; idx += 256) {
        int head = idx >> 7;
        int d = idx & 127;
        float x = base[idx];
        if (head < NH + KVH) {
            float c  = rcos[pos * HD + d];
            float sn = rsin[pos * HD + d];
            float other = (d < 64) ? -base[head*HD + d + 64]
                                   :  base[head*HD + d - 64];
            float val = x * c + other * sn;
            if (head < NH) {
                Qo[(((size_t)(b*NH + head)) * SEQ + s) * HD + d] = val * QSCALE;
            } else {
                Ko[(((size_t)(b*KVH + head - NH)) * SEQ + s) * HD + d] = val;
            }
        } else {
            Vo[(((size_t)(b*KVH + head - NH - KVH)) * SEQ + s) * HD + d] = x;
        }
    }
}

// ---------------------------------------------------------------------------
// Flash attention (causal, GQA) — fp32 SIMT
// ---------------------------------------------------------------------------
__global__ void __launch_bounds__(256, 1)
attn_kernel(const float* __restrict__ Q, const float* __restrict__ K,
            const float* __restrict__ V, const int* __restrict__ amask,
            float* __restrict__ Out)
{
    extern __shared__ float smf[];
    float* Qs = smf;
    float* Ks = Qs + 64*129;
    float* Vs = Ks + 64*129;
    float* Ss = Vs + 64*128;
    float* mS  = Ss + 64*65;
    float* lS  = mS + 64;
    float* scS = lS + 64;
    float* mk  = scS + 64;

    int tid = threadIdx.x;
    int qt = blockIdx.x;
    int h  = blockIdx.y;
    int b  = blockIdx.z;
    int kvh = h >> 2;

    const float* Qg = Q + ((size_t)(b*NH + h) * SEQ + qt*64) * HD;
    const float* Kg = K + ((size_t)(b*KVH + kvh) * SEQ) * HD;
    const float* Vg = V + ((size_t)(b*KVH + kvh) * SEQ) * HD;

    for (int i = tid; i < 64*128; i += 256) {
        int r = i >> 7, d = i & 127;
        Qs[r*129 + d] = Qg[(size_t)r*HD + d];
    }
    if (tid < 64) { mS[tid] = -1e30f; lS[tid] = 0.f; }

    float o[32];
    #pragma unroll
    for (int j = 0; j < 32; j++) o[j] = 0.f;

    int orow = tid & 63;
    int od   = (tid >> 6) * 32;
    int tr = tid >> 4, tc = tid & 15;

    for (int kt = 0; kt <= qt; kt++) {
        __syncthreads();
        for (int i = tid; i < 64*128; i += 256) {
            int r = i >> 7, d = i & 127;
            Ks[r*129 + d] = Kg[(size_t)(kt*64 + r)*HD + d];
            Vs[r*128 + d] = Vg[(size_t)(kt*64 + r)*HD + d];
        }
        if (tid < 64)
            mk[tid] = (amask[b*SEQ + kt*64 + tid] > 0) ? 0.f : -1e30f;
        __syncthreads();

        float acc[4][4];
        #pragma unroll
        for (int i = 0; i < 4; i++)
            #pragma unroll
            for (int j = 0; j < 4; j++) acc[i][j] = 0.f;

        #pragma unroll 4
        for (int kk = 0; kk < 128; kk++) {
            float a0 = Qs[(tr*4+0)*129 + kk];
            float a1 = Qs[(tr*4+1)*129 + kk];
            float a2 = Qs[(tr*4+2)*129 + kk];
            float a3 = Qs[(tr*4+3)*129 + kk];
            float b0 = Ks[(tc*4+0)*129 + kk];
            float b1 = Ks[(tc*4+1)*129 + kk];
            float b2 = Ks[(tc*4+2)*129 + kk];
            float b3 = Ks[(tc*4+3)*129 + kk];
            acc[0][0] += a0*b0; acc[0][1] += a0*b1; acc[0][2] += a0*b2; acc[0][3] += a0*b3;
            acc[1][0] += a1*b0; acc[1][1] += a1*b1; acc[1][2] += a1*b2; acc[1][3] += a1*b3;
            acc[2][0] += a2*b0; acc[2][1] += a2*b1; acc[2][2] += a2*b2; acc[2][3] += a2*b3;
            acc[3][0] += a3*b0; acc[3][1] += a3*b1; acc[3][2] += a3*b2; acc[3][3] += a3*b3;
        }

        int rg0 = qt*64 + tr*4;
        int cg0 = kt*64 + tc*4;
        #pragma unroll
        for (int i = 0; i < 4; i++)
            #pragma unroll
            for (int j = 0; j < 4; j++) {
                float v = acc[i][j] + mk[tc*4 + j];
                if (cg0 + j > rg0 + i) v = -1e30f;
                Ss[(tr*4+i)*65 + tc*4 + j] = v;
            }
        __syncthreads();

        if (tid < 64) {
            int r = tid;
            float mo = mS[r];
            float mx = mo;
            #pragma unroll 8
            for (int c = 0; c < 64; c++) mx = fmaxf(mx, Ss[r*65 + c]);
            float sc = __expf(mo - mx);
            float l = lS[r] * sc;
            #pragma unroll 8
            for (int c = 0; c < 64; c++) {
                float p = __expf(Ss[r*65 + c] - mx);
                Ss[r*65 + c] = p;
                l += p;
            }
            mS[r] = mx; lS[r] = l; scS[r] = sc;
        }
        __syncthreads();

        float sc = scS[orow];
        #pragma unroll
        for (int j = 0; j < 32; j++) o[j] *= sc;
        #pragma unroll 2
        for (int k = 0; k < 64; k++) {
            float p = Ss[orow*65 + k];
            const float4* vr = (const float4*)&Vs[k*128 + od];
            #pragma unroll
            for (int j4 = 0; j4 < 8; j4++) {
                float4 v = vr[j4];
                o[j4*4+0] += p*v.x;
                o[j4*4+1] += p*v.y;
                o[j4*4+2] += p*v.z;
                o[j4*4+3] += p*v.w;
            }
        }
    }

    float inv = 1.f / lS[orow];
    int row = qt*64 + orow;
    float* og = Out + (((size_t)(b*SEQ + row)) * NH + h) * HD + od;
    #pragma unroll
    for (int j4 = 0; j4 < 8; j4++) {
        float4 v;
        v.x = o[j4*4+0] * inv;
        v.y = o[j4*4+1] * inv;
        v.z = o[j4*4+2] * inv;
        v.w = o[j4*4+3] * inv;
        *(float4*)&og[j4*4] = v;
    }
}

// ---------------------------------------------------------------------------
// kernel_launch
// ---------------------------------------------------------------------------
extern "C" void kernel_launch(void* const* d_in, const int* in_sizes, int n_in,
                              void* d_out, int out_size)
{
    const float* hidden = (const float*)d_in[0];
    const int*   amask  = (const int*)  d_in[1];
    const int*   posids = (const int*)  d_in[2];
    const float* wqkv   = (const float*)d_in[3];
    const float* w_out  = (const float*)d_in[4];
    const float* n1w    = (const float*)d_in[5];
    const float* n2w    = (const float*)d_in[6];
    const float* rsin   = (const float*)d_in[7];
    const float* rcos   = (const float*)d_in[8];
    float* out = (float*)d_out;

    float *p_qkv, *p_q, *p_k, *p_v, *p_attn;
    __nv_bfloat16 *p_xnh, *p_xnl, *p_ath, *p_atl, *p_wqh, *p_wql, *p_woh, *p_wol;
    cudaGetSymbolAddress((void**)&p_qkv,  g_qkv);
    cudaGetSymbolAddress((void**)&p_q,    g_q);
    cudaGetSymbolAddress((void**)&p_k,    g_k);
    cudaGetSymbolAddress((void**)&p_v,    g_v);
    cudaGetSymbolAddress((void**)&p_attn, g_attn);
    cudaGetSymbolAddress((void**)&p_xnh,  g_xn_h);
    cudaGetSymbolAddress((void**)&p_xnl,  g_xn_l);
    cudaGetSymbolAddress((void**)&p_ath,  g_at_h);
    cudaGetSymbolAddress((void**)&p_atl,  g_at_l);
    cudaGetSymbolAddress((void**)&p_wqh,  g_wq_h);
    cudaGetSymbolAddress((void**)&p_wql,  g_wq_l);
    cudaGetSymbolAddress((void**)&p_woh,  g_wo_h);
    cudaGetSymbolAddress((void**)&p_wol,  g_wo_l);

    cudaFuncSetAttribute(hgemm_kernel<0>,
                         cudaFuncAttributeMaxDynamicSharedMemorySize, HG_SMEM);
    cudaFuncSetAttribute(hgemm_kernel<1>,
                         cudaFuncAttributeMaxDynamicSharedMemorySize, HG_SMEM);
    int asmem = (64*129*2 + 64*128 + 64*65 + 64*4) * sizeof(float);
    cudaFuncSetAttribute(attn_kernel,
                         cudaFuncAttributeMaxDynamicSharedMemorySize, asmem);

    // 1. pre-norm -> bf16 hi/lo
    rmsnorm_split_kernel<<<BS, 256>>>(hidden, n1w, p_xnh, p_xnl);

    // weight conversions
    split_kernel<<<(DM*QKV_N/4 + 255)/256, 256>>>(wqkv, p_wqh, p_wql, DM*QKV_N/4);
    split_kernel<<<(DM*DM/4 + 255)/256, 256>>>(w_out, p_woh, p_wol, DM*DM/4);

    // 2. QKV projection + clip (HMMA bfx3)
    {
        dim3 grid(QKV_N/128, BS/128);
        hgemm_kernel<0><<<grid, 256, HG_SMEM>>>(p_xnh, p_xnl, p_wqh, p_wql,
                                                nullptr, p_qkv, BS, QKV_N, DM);
    }

    // 3. RoPE + split
    rope_kernel<<<BS, 256>>>(p_qkv, posids, rsin, rcos, p_q, p_k, p_v);

    // 4. flash attention (fp32)
    {
        dim3 grid(SEQ/64, NH, BATCH);
        attn_kernel<<<grid, 256, asmem>>>(p_q, p_k, p_v, amask, p_attn);
    }

    // 5. out-proj + residual add (HMMA bfx3)
    split_kernel<<<(BS*DM/4 + 255)/256, 256>>>(p_attn, p_ath, p_atl, BS*DM/4);
    {
        dim3 grid(DM/128, BS/128);
        hgemm_kernel<1><<<grid, 256, HG_SMEM>>>(p_ath, p_atl, p_woh, p_wol,
                                                hidden, out, BS, DM, DM);
    }

    // 6. post-norm
    rmsnorm_kernel<<<BS, 256>>>(out, n2w, out + (size_t)BS * DM);
}

// round 4
// speedup vs baseline: 2.9219x; 1.9694x over previous
#include <cuda_runtime.h>
#include <cuda_bf16.h>
#include <math.h>
#include <stdint.h>

// Problem constants
#define BATCH   2
#define SEQ     2048
#define DM      2048
#define NH      16
#define KVH     4
#define HD      128
#define QKV_N   3072
#define BS      (BATCH*SEQ)   // 4096
#define QSCALE  0.08838834764831845f

// ---------------------------------------------------------------------------
// Scratch
// ---------------------------------------------------------------------------
__device__ float g_qkv [BS * QKV_N];

__device__ __nv_bfloat16 g_xn_h [BS * DM];
__device__ __nv_bfloat16 g_xn_l [BS * DM];
__device__ __nv_bfloat16 g_at_h [BS * DM];
__device__ __nv_bfloat16 g_at_l [BS * DM];
__device__ __nv_bfloat16 g_wq_h [DM * QKV_N];
__device__ __nv_bfloat16 g_wq_l [DM * QKV_N];
__device__ __nv_bfloat16 g_wo_h [DM * DM];
__device__ __nv_bfloat16 g_wo_l [DM * DM];

__device__ __nv_bfloat16 g_qh [BATCH * NH  * SEQ * HD];
__device__ __nv_bfloat16 g_ql [BATCH * NH  * SEQ * HD];
__device__ __nv_bfloat16 g_kh [BATCH * KVH * SEQ * HD];
__device__ __nv_bfloat16 g_kl [BATCH * KVH * SEQ * HD];
__device__ __nv_bfloat16 g_vh [BATCH * KVH * SEQ * HD];
__device__ __nv_bfloat16 g_vl [BATCH * KVH * SEQ * HD];

// ---------------------------------------------------------------------------
// PTX helpers (compute_103-safe)
// ---------------------------------------------------------------------------
__device__ __forceinline__ uint32_t smem_u32(const void* p) {
    uint32_t a;
    asm("{ .reg .u64 t; cvta.to.shared.u64 t, %1; cvt.u32.u64 %0, t; }"
        : "=r"(a) : "l"(p));
    return a;
}
__device__ __forceinline__ void cp16(uint32_t dst, const void* src) {
    asm volatile("cp.async.cg.shared.global [%0], [%1], 16;"
                 :: "r"(dst), "l"(src));
}
__device__ __forceinline__ void cp_commit() {
    asm volatile("cp.async.commit_group;" ::: "memory");
}
template<int N>
__device__ __forceinline__ void cp_wait() {
    asm volatile("cp.async.wait_group %0;" :: "n"(N) : "memory");
}
__device__ __forceinline__ void ldsm_x4(uint32_t* r, uint32_t addr) {
    asm volatile("ldmatrix.sync.aligned.m8n8.x4.shared.b16 {%0,%1,%2,%3}, [%4];"
                 : "=r"(r[0]), "=r"(r[1]), "=r"(r[2]), "=r"(r[3]) : "r"(addr));
}
__device__ __forceinline__ void ldsm_x4t(uint32_t* r, uint32_t addr) {
    asm volatile("ldmatrix.sync.aligned.m8n8.x4.trans.shared.b16 {%0,%1,%2,%3}, [%4];"
                 : "=r"(r[0]), "=r"(r[1]), "=r"(r[2]), "=r"(r[3]) : "r"(addr));
}
__device__ __forceinline__ void mma_bf16(float* d, const uint32_t* a, const uint32_t* b) {
    asm volatile(
        "mma.sync.aligned.m16n8k16.row.col.f32.bf16.bf16.f32 "
        "{%0,%1,%2,%3}, {%4,%5,%6,%7}, {%8,%9}, {%0,%1,%2,%3};"
        : "+f"(d[0]), "+f"(d[1]), "+f"(d[2]), "+f"(d[3])
        : "r"(a[0]), "r"(a[1]), "r"(a[2]), "r"(a[3]), "r"(b[0]), "r"(b[1]));
}
__device__ __forceinline__ void mma_bf16_2(float* d, const uint32_t* a,
                                           uint32_t b0, uint32_t b1) {
    asm volatile(
        "mma.sync.aligned.m16n8k16.row.col.f32.bf16.bf16.f32 "
        "{%0,%1,%2,%3}, {%4,%5,%6,%7}, {%8,%9}, {%0,%1,%2,%3};"
        : "+f"(d[0]), "+f"(d[1]), "+f"(d[2]), "+f"(d[3])
        : "r"(a[0]), "r"(a[1]), "r"(a[2]), "r"(a[3]), "r"(b0), "r"(b1));
}

// ---------------------------------------------------------------------------
// RMSNorm (fp32 out)
// ---------------------------------------------------------------------------
__global__ void rmsnorm_kernel(const float* __restrict__ x,
                               const float* __restrict__ w,
                               float* __restrict__ y)
{
    __shared__ float red[256];
    int row = blockIdx.x;
    const float4* xr = (const float4*)(x + (size_t)row * DM);
    float s = 0.f;
    #pragma unroll
    for (int i = threadIdx.x; i < DM/4; i += 256) {
        float4 v = xr[i];
        s += v.x*v.x + v.y*v.y + v.z*v.z + v.w*v.w;
    }
    red[threadIdx.x] = s;
    __syncthreads();
    for (int st = 128; st > 0; st >>= 1) {
        if (threadIdx.x < st) red[threadIdx.x] += red[threadIdx.x + st];
        __syncthreads();
    }
    float rs = rsqrtf(red[0] * (1.0f/(float)DM) + 1e-5f);
    float4* yr = (float4*)(y + (size_t)row * DM);
    const float4* wr = (const float4*)w;
    #pragma unroll
    for (int i = threadIdx.x; i < DM/4; i += 256) {
        float4 v = xr[i];
        float4 ww = wr[i];
        v.x = v.x * rs * ww.x;
        v.y = v.y * rs * ww.y;
        v.z = v.z * rs * ww.z;
        v.w = v.w * rs * ww.w;
        yr[i] = v;
    }
}

// RMSNorm -> bf16 hi/lo split output
__global__ void rmsnorm_split_kernel(const float* __restrict__ x,
                                     const float* __restrict__ w,
                                     __nv_bfloat16* __restrict__ yh,
                                     __nv_bfloat16* __restrict__ yl)
{
    __shared__ float red[256];
    int row = blockIdx.x;
    const float4* xr = (const float4*)(x + (size_t)row * DM);
    float s = 0.f;
    #pragma unroll
    for (int i = threadIdx.x; i < DM/4; i += 256) {
        float4 v = xr[i];
        s += v.x*v.x + v.y*v.y + v.z*v.z + v.w*v.w;
    }
    red[threadIdx.x] = s;
    __syncthreads();
    for (int st = 128; st > 0; st >>= 1) {
        if (threadIdx.x < st) red[threadIdx.x] += red[threadIdx.x + st];
        __syncthreads();
    }
    float rs = rsqrtf(red[0] * (1.0f/(float)DM) + 1e-5f);
    const float4* wr = (const float4*)w;
    #pragma unroll
    for (int i = threadIdx.x; i < DM/4; i += 256) {
        float4 v = xr[i];
        float4 ww = wr[i];
        float f[4] = {v.x*rs*ww.x, v.y*rs*ww.y, v.z*rs*ww.z, v.w*rs*ww.w};
        __nv_bfloat16 h[4], l[4];
        #pragma unroll
        for (int j = 0; j < 4; j++) {
            h[j] = __float2bfloat16(f[j]);
            l[j] = __float2bfloat16(f[j] - __bfloat162float(h[j]));
        }
        size_t o = (size_t)row * DM + i*4;
        *(ulonglong1*)&yh[o] = *(ulonglong1*)h;
        *(ulonglong1*)&yl[o] = *(ulonglong1*)l;
    }
}

// fp32 -> bf16 hi/lo split
__global__ void split_kernel(const float* __restrict__ x,
                             __nv_bfloat16* __restrict__ xh,
                             __nv_bfloat16* __restrict__ xl, int n4)
{
    int i = blockIdx.x * blockDim.x + threadIdx.x;
    if (i >= n4) return;
    float4 v = ((const float4*)x)[i];
    float f[4] = {v.x, v.y, v.z, v.w};
    __nv_bfloat16 h[4], l[4];
    #pragma unroll
    for (int j = 0; j < 4; j++) {
        h[j] = __float2bfloat16(f[j]);
        l[j] = __float2bfloat16(f[j] - __bfloat162float(h[j]));
    }
    *(ulonglong1*)&xh[(size_t)i*4] = *(ulonglong1*)h;
    *(ulonglong1*)&xl[(size_t)i*4] = *(ulonglong1*)l;
}

// ---------------------------------------------------------------------------
// HMMA GEMM (bfx3), CTA 128x128, k-chunk 32. EPI 0: clip. EPI 1: +Resid.
// ---------------------------------------------------------------------------
#define A_STRIDE  80
#define B_STRIDE  272
#define AH_OFF    0
#define AL_OFF    10240
#define BH_OFF    20480
#define BL_OFF    29184
#define CHUNK_SZ  37888
#define HG_SMEM   (2*CHUNK_SZ)

template<int EPI>
__global__ void __launch_bounds__(256)
hgemm_kernel(const __nv_bfloat16* __restrict__ Ah, const __nv_bfloat16* __restrict__ Al,
             const __nv_bfloat16* __restrict__ Bh, const __nv_bfloat16* __restrict__ Bl,
             const float* __restrict__ Resid, float* __restrict__ C,
             int M, int N, int K)
{
    extern __shared__ char sm[];
    uint32_t sb = smem_u32(sm);

    int tid  = threadIdx.x;
    int lane = tid & 31;
    int warp = tid >> 5;
    int warpM = warp & 1;
    int warpN = warp >> 1;
    int rowBase = blockIdx.y * 128;
    int colBase = blockIdx.x * 128;

    float acc[4][4][4];
    #pragma unroll
    for (int i = 0; i < 4; i++)
        #pragma unroll
        for (int j = 0; j < 4; j++)
            #pragma unroll
            for (int q = 0; q < 4; q++) acc[i][j][q] = 0.f;

    int nC = K / 32;

    auto issue = [&](int c) {
        int buf = c & 1;
        uint32_t base = sb + buf * CHUNK_SZ;
        int k0 = c * 32;
        #pragma unroll
        for (int it = 0; it < 2; it++) {
            int idx = it * 256 + tid;
            int r  = idx >> 2;
            int kc = idx & 3;
            size_t go = (size_t)(rowBase + r) * K + k0 + kc*8;
            uint32_t so = r * A_STRIDE + kc * 16;
            cp16(base + AH_OFF + so, Ah + go);
            cp16(base + AL_OFF + so, Al + go);
        }
        #pragma unroll
        for (int it = 0; it < 2; it++) {
            int idx = it * 256 + tid;
            int r   = idx >> 4;
            int c16 = idx & 15;
            size_t go = (size_t)(k0 + r) * N + colBase + c16*8;
            uint32_t so = r * B_STRIDE + c16 * 16;
            cp16(base + BH_OFF + so, Bh + go);
            cp16(base + BL_OFF + so, Bl + go);
        }
        cp_commit();
    };

    issue(0);

    for (int c = 0; c < nC; c++) {
        if (c + 1 < nC) { issue(c + 1); cp_wait<1>(); }
        else            { cp_wait<0>(); }
        __syncthreads();

        uint32_t base = sb + (c & 1) * CHUNK_SZ;

        #pragma unroll
        for (int kk = 0; kk < 2; kk++) {
            uint32_t aR[2][4][4];
            #pragma unroll
            for (int mt = 0; mt < 4; mt++) {
                int r = warpM*64 + mt*16 + (lane & 15);
                uint32_t col = ((lane >> 4) * 16) + kk * 32;
                ldsm_x4(aR[0][mt], base + AH_OFF + r*A_STRIDE + col);
                ldsm_x4(aR[1][mt], base + AL_OFF + r*A_STRIDE + col);
            }
            uint32_t bR[2][2][4];
            #pragma unroll
            for (int nt = 0; nt < 2; nt++) {
                int r = kk*16 + (lane & 15);
                uint32_t col = (uint32_t)(warpN*32 + nt*16) * 2 + ((lane >> 4) * 16);
                ldsm_x4t(bR[0][nt], base + BH_OFF + r*B_STRIDE + col);
                ldsm_x4t(bR[1][nt], base + BL_OFF + r*B_STRIDE + col);
            }
            #pragma unroll
            for (int mt = 0; mt < 4; mt++) {
                #pragma unroll
                for (int n8 = 0; n8 < 4; n8++) {
                    int nt = n8 >> 1, hf = (n8 & 1) * 2;
                    mma_bf16(acc[mt][n8], aR[0][mt], &bR[0][nt][hf]);
                    mma_bf16(acc[mt][n8], aR[0][mt], &bR[1][nt][hf]);
                    mma_bf16(acc[mt][n8], aR[1][mt], &bR[0][nt][hf]);
                }
            }
        }
        __syncthreads();
    }

    int rg = lane >> 2;
    int cg = (lane & 3) * 2;
    #pragma unroll
    for (int mt = 0; mt < 4; mt++) {
        #pragma unroll
        for (int n8 = 0; n8 < 4; n8++) {
            int r0 = rowBase + warpM*64 + mt*16 + rg;
            int cc = colBase + warpN*32 + n8*8 + cg;
            #pragma unroll
            for (int half = 0; half < 2; half++) {
                int r = r0 + half * 8;
                float2 v;
                v.x = acc[mt][n8][half*2+0];
                v.y = acc[mt][n8][half*2+1];
                if (EPI == 0) {
                    v.x = fminf(8.f, fmaxf(-8.f, v.x));
                    v.y = fminf(8.f, fmaxf(-8.f, v.y));
                } else {
                    float2 rv = *(const float2*)&Resid[(size_t)r * N + cc];
                    v.x += rv.x; v.y += rv.y;
                }
                *(float2*)&C[(size_t)r * N + cc] = v;
            }
        }
    }
}

// ---------------------------------------------------------------------------
// RoPE + split to bf16 hi/lo Q/K/V
// ---------------------------------------------------------------------------
__global__ void rope_kernel(const float* __restrict__ qkv,
                            const int* __restrict__ posids,
                            const float* __restrict__ rsin,
                            const float* __restrict__ rcos,
                            __nv_bfloat16* __restrict__ Qh, __nv_bfloat16* __restrict__ Ql,
                            __nv_bfloat16* __restrict__ Kh, __nv_bfloat16* __restrict__ Kl,
                            __nv_bfloat16* __restrict__ Vh, __nv_bfloat16* __restrict__ Vl)
{
    int bs = blockIdx.x;
    int b = bs >> 11;
    int s = bs & 2047;
    int pos = posids[bs];
    const float* base = qkv + (size_t)bs * QKV_N;

    for (int idx = threadIdx.x; idx < QKV_N; idx += 256) {
        int head = idx >> 7;
        int d = idx & 127;
        float x = base[idx];
        float val;
        size_t o;
        __nv_bfloat16* Dh;
        __nv_bfloat16* Dl;
        if (head < NH + KVH) {
            float c  = rcos[pos * HD + d];
            float sn = rsin[pos * HD + d];
            float other = (d < 64) ? -base[head*HD + d + 64]
                                   :  base[head*HD + d - 64];
            val = x * c + other * sn;
            if (head < NH) {
                val *= QSCALE;
                o = (((size_t)(b*NH + head)) * SEQ + s) * HD + d;
                Dh = Qh; Dl = Ql;
            } else {
                o = (((size_t)(b*KVH + head - NH)) * SEQ + s) * HD + d;
                Dh = Kh; Dl = Kl;
            }
        } else {
            val = x;
            o = (((size_t)(b*KVH + head - NH - KVH)) * SEQ + s) * HD + d;
            Dh = Vh; Dl = Vl;
        }
        __nv_bfloat16 h = __float2bfloat16(val);
        __nv_bfloat16 l = __float2bfloat16(val - __bfloat162float(h));
        Dh[o] = h;
        Dl[o] = l;
    }
}

// ---------------------------------------------------------------------------
// Flash attention, HMMA bfx3. BM=64, BN=64, HD=128, 8 warps, 256 thr.
// K stored [n][k] (non-trans ldsm B), V stored [k][n] (trans ldsm B).
// Output written as bf16 hi/lo [bs, 2048].
// ---------------------------------------------------------------------------
#define AT_QKV_STRIDE 272      // bytes per 128-col bf16 row (128*2 + 16 pad)
#define AT_P_STRIDE   144      // bytes per 64-col bf16 row (64*2 + 16 pad)
#define AT_S_STRIDE   66       // floats
#define AQH 0
#define AQL 17408
#define AKV 34816
#define AKV_BUF 69632          // Kh 0 | Kl 17408 | Vh 34816 | Vl 52224
#define AS_OFF  174080
#define APH 190976
#define APL 200192
#define AST 209408             // mS[64] lS[64] scS[64] mk[64]
#define ATT_SMEM 210432

__global__ void __launch_bounds__(256, 1)
attn_mma_kernel(const __nv_bfloat16* __restrict__ Qh, const __nv_bfloat16* __restrict__ Ql,
                const __nv_bfloat16* __restrict__ Kh, const __nv_bfloat16* __restrict__ Kl,
                const __nv_bfloat16* __restrict__ Vh, const __nv_bfloat16* __restrict__ Vl,
                const int* __restrict__ amask,
                __nv_bfloat16* __restrict__ Oh, __nv_bfloat16* __restrict__ Ol)
{
    extern __shared__ char sm[];
    uint32_t sb = smem_u32(sm);
    float* Sarr = (float*)(sm + AS_OFF);
    float* mS   = (float*)(sm + AST);
    float* lS   = mS + 64;
    float* scS  = lS + 64;
    float* mk   = scS + 64;

    int tid  = threadIdx.x;
    int lane = tid & 31;
    int warp = tid >> 5;
    int wm = warp & 3;          // row group (16 rows)
    int wn = warp >> 2;         // col half
    int qt = blockIdx.x;
    int h  = blockIdx.y;
    int b  = blockIdx.z;
    int kvh = h >> 2;

    const __nv_bfloat16* Qgh = Qh + ((size_t)(b*NH + h) * SEQ + qt*64) * HD;
    const __nv_bfloat16* Qgl = Ql + ((size_t)(b*NH + h) * SEQ + qt*64) * HD;
    const __nv_bfloat16* Kgh = Kh + ((size_t)(b*KVH + kvh) * SEQ) * HD;
    const __nv_bfloat16* Kgl = Kl + ((size_t)(b*KVH + kvh) * SEQ) * HD;
    const __nv_bfloat16* Vgh = Vh + ((size_t)(b*KVH + kvh) * SEQ) * HD;
    const __nv_bfloat16* Vgl = Vl + ((size_t)(b*KVH + kvh) * SEQ) * HD;

    // load Q tiles (hi/lo)
    #pragma unroll
    for (int it = 0; it < 4; it++) {
        int idx = it * 256 + tid;       // 0..1023
        int r = idx >> 4;
        int c = idx & 15;
        size_t go = (size_t)r * HD + c*8;
        uint32_t so = r * AT_QKV_STRIDE + c*16;
        cp16(sb + AQH + so, Qgh + go);
        cp16(sb + AQL + so, Qgl + go);
    }
    cp_commit();

    auto issueKV = [&](int kt) {
        uint32_t base = sb + AKV + (kt & 1) * AKV_BUF;
        #pragma unroll
        for (int it = 0; it < 4; it++) {
            int idx = it * 256 + tid;
            int r = idx >> 4;
            int c = idx & 15;
            size_t go = (size_t)(kt*64 + r) * HD + c*8;
            uint32_t so = r * AT_QKV_STRIDE + c*16;
            cp16(base + 0     + so, Kgh + go);
            cp16(base + 17408 + so, Kgl + go);
            cp16(base + 34816 + so, Vgh + go);
            cp16(base + 52224 + so, Vgl + go);
        }
        cp_commit();
    };
    issueKV(0);

    if (tid < 64) { mS[tid] = -1e30f; lS[tid] = 0.f; }

    float o[8][4];
    #pragma unroll
    for (int i = 0; i < 8; i++)
        #pragma unroll
        for (int j = 0; j < 4; j++) o[i][j] = 0.f;

    for (int kt = 0; kt <= qt; kt++) {
        if (kt < qt) { issueKV(kt + 1); cp_wait<1>(); }
        else         { cp_wait<0>(); }
        __syncthreads();

        if (tid < 64)
            mk[tid] = (amask[b*SEQ + kt*64 + tid] > 0) ? 0.f : -1e30f;

        uint32_t kvbase = sb + AKV + (kt & 1) * AKV_BUF;

        // ---- S = Q @ K^T : warp tile 16x32 ----
        float sacc[4][4];
        #pragma unroll
        for (int i = 0; i < 4; i++)
            #pragma unroll
            for (int j = 0; j < 4; j++) sacc[i][j] = 0.f;

        #pragma unroll
        for (int kk = 0; kk < 8; kk++) {
            uint32_t aH[4], aL[4];
            uint32_t aoff = (wm*16 + (lane & 15)) * AT_QKV_STRIDE
                          + kk*32 + ((lane >> 4) * 16);
            ldsm_x4(aH, sb + AQH + aoff);
            ldsm_x4(aL, sb + AQL + aoff);
            uint32_t bH[2][4], bL[2][4];
            #pragma unroll
            for (int nt = 0; nt < 2; nt++) {
                uint32_t nrow = wn*32 + nt*16 + (lane & 15);
                uint32_t boff = nrow * AT_QKV_STRIDE + kk*32 + ((lane >> 4) * 16);
                ldsm_x4(bH[nt], kvbase + 0     + boff);
                ldsm_x4(bL[nt], kvbase + 17408 + boff);
            }
            // non-trans B: n8 even -> regs {0,2}; odd -> {1,3}
            #pragma unroll
            for (int n8 = 0; n8 < 4; n8++) {
                int nt = n8 >> 1;
                int lo = n8 & 1;
                mma_bf16_2(sacc[n8], aH, bH[nt][lo], bH[nt][lo+2]);
                mma_bf16_2(sacc[n8], aH, bL[nt][lo], bL[nt][lo+2]);
                mma_bf16_2(sacc[n8], aL, bH[nt][lo], bH[nt][lo+2]);
            }
        }
        // write S frags to smem
        #pragma unroll
        for (int n8 = 0; n8 < 4; n8++) {
            #pragma unroll
            for (int half = 0; half < 2; half++) {
                int r = wm*16 + (lane >> 2) + half*8;
                int c = wn*32 + n8*8 + (lane & 3)*2;
                float2 v;
                v.x = sacc[n8][half*2+0];
                v.y = sacc[n8][half*2+1];
                *(float2*)&Sarr[r*AT_S_STRIDE + c] = v;
            }
        }
        __syncthreads();

        // ---- online softmax: 4 threads per row ----
        {
            int r = tid >> 2, q = tid & 3;
            int rg = qt*64 + r;
            float mo = mS[r];
            float lold = lS[r];
            float sv[16];
            float mx = mo;
            #pragma unroll
            for (int i = 0; i < 16; i++) {
                int c = q*16 + i;
                float s = Sarr[r*AT_S_STRIDE + c] + mk[c];
                if (kt*64 + c > rg) s = -1e30f;
                sv[i] = s;
                mx = fmaxf(mx, s);
            }
            mx = fmaxf(mx, __shfl_xor_sync(0xffffffff, mx, 1));
            mx = fmaxf(mx, __shfl_xor_sync(0xffffffff, mx, 2));
            float l = 0.f;
            __nv_bfloat16* PhRow = (__nv_bfloat16*)(sm + APH + r*AT_P_STRIDE);
            __nv_bfloat16* PlRow = (__nv_bfloat16*)(sm + APL + r*AT_P_STRIDE);
            #pragma unroll
            for (int i = 0; i < 16; i += 2) {
                float p0 = __expf(sv[i]   - mx);
                float p1 = __expf(sv[i+1] - mx);
                l += p0 + p1;
                __nv_bfloat16 h0 = __float2bfloat16(p0);
                __nv_bfloat16 h1 = __float2bfloat16(p1);
                __nv_bfloat16 l0 = __float2bfloat16(p0 - __bfloat162float(h0));
                __nv_bfloat16 l1 = __float2bfloat16(p1 - __bfloat162float(h1));
                __nv_bfloat162 ph; ph.x = h0; ph.y = h1;
                __nv_bfloat162 pl; pl.x = l0; pl.y = l1;
                *(__nv_bfloat162*)&PhRow[q*16 + i] = ph;
                *(__nv_bfloat162*)&PlRow[q*16 + i] = pl;
            }
            l += __shfl_xor_sync(0xffffffff, l, 1);
            l += __shfl_xor_sync(0xffffffff, l, 2);
            float sc = __expf(mo - mx);
            if (q == 0) {
                mS[r] = mx;
                lS[r] = lold * sc + l;
                scS[r] = sc;
            }
        }
        __syncthreads();

        // ---- O = O*sc + P @ V : warp tile 16x64 ----
        {
            float sc0 = scS[wm*16 + (lane >> 2)];
            float sc1 = scS[wm*16 + (lane >> 2) + 8];
            #pragma unroll
            for (int n8 = 0; n8 < 8; n8++) {
                o[n8][0] *= sc0; o[n8][1] *= sc0;
                o[n8][2] *= sc1; o[n8][3] *= sc1;
            }
            #pragma unroll
            for (int ks = 0; ks < 4; ks++) {
                uint32_t aPH[4], aPL[4];
                uint32_t poff = (wm*16 + (lane & 15)) * AT_P_STRIDE
                              + ks*32 + ((lane >> 4) * 16);
                ldsm_x4(aPH, sb + APH + poff);
                ldsm_x4(aPL, sb + APL + poff);
                uint32_t vH[4][4], vL[4][4];
                #pragma unroll
                for (int nt = 0; nt < 4; nt++) {
                    uint32_t voff = (uint32_t)(ks*16 + (lane & 15)) * AT_QKV_STRIDE
                                  + (uint32_t)(wn*64 + nt*16)*2 + ((lane >> 4) * 16);
                    ldsm_x4t(vH[nt], kvbase + 34816 + voff);
                    ldsm_x4t(vL[nt], kvbase + 52224 + voff);
                }
                #pragma unroll
                for (int n8 = 0; n8 < 8; n8++) {
                    int nt = n8 >> 1, hf = (n8 & 1) * 2;
                    mma_bf16(o[n8], aPH, &vH[nt][hf]);
                    mma_bf16(o[n8], aPH, &vL[nt][hf]);
                    mma_bf16(o[n8], aPL, &vH[nt][hf]);
                }
            }
        }
        __syncthreads();
    }

    // ---- epilogue: O /= l, write bf16 hi/lo ----
    {
        int r0l = wm*16 + (lane >> 2);
        float inv0 = 1.f / lS[r0l];
        float inv1 = 1.f / lS[r0l + 8];
        #pragma unroll
        for (int half = 0; half < 2; half++) {
            int rloc = r0l + half*8;
            int rg = qt*64 + rloc;
            float inv = half ? inv1 : inv0;
            size_t rowoff = (size_t)(b*SEQ + rg) * DM + (size_t)h * HD;
            #pragma unroll
            for (int n8 = 0; n8 < 8; n8++) {
                int c = wn*64 + n8*8 + (lane & 3)*2;
                float f0 = o[n8][half*2+0] * inv;
                float f1 = o[n8][half*2+1] * inv;
                __nv_bfloat16 h0 = __float2bfloat16(f0);
                __nv_bfloat16 h1 = __float2bfloat16(f1);
                __nv_bfloat16 g0 = __float2bfloat16(f0 - __bfloat162float(h0));
                __nv_bfloat16 g1 = __float2bfloat16(f1 - __bfloat162float(h1));
                __nv_bfloat162 ph; ph.x = h0; ph.y = h1;
                __nv_bfloat162 pl; pl.x = g0; pl.y = g1;
                *(__nv_bfloat162*)&Oh[rowoff + c] = ph;
                *(__nv_bfloat162*)&Ol[rowoff + c] = pl;
            }
        }
    }
}

// ---------------------------------------------------------------------------
// kernel_launch
// ---------------------------------------------------------------------------
extern "C" void kernel_launch(void* const* d_in, const int* in_sizes, int n_in,
                              void* d_out, int out_size)
{
    const float* hidden = (const float*)d_in[0];
    const int*   amask  = (const int*)  d_in[1];
    const int*   posids = (const int*)  d_in[2];
    const float* wqkv   = (const float*)d_in[3];
    const float* w_out  = (const float*)d_in[4];
    const float* n1w    = (const float*)d_in[5];
    const float* n2w    = (const float*)d_in[6];
    const float* rsin   = (const float*)d_in[7];
    const float* rcos   = (const float*)d_in[8];
    float* out = (float*)d_out;

    float *p_qkv;
    __nv_bfloat16 *p_xnh, *p_xnl, *p_ath, *p_atl, *p_wqh, *p_wql, *p_woh, *p_wol;
    __nv_bfloat16 *p_qh, *p_ql, *p_kh, *p_kl, *p_vh, *p_vl;
    cudaGetSymbolAddress((void**)&p_qkv,  g_qkv);
    cudaGetSymbolAddress((void**)&p_xnh,  g_xn_h);
    cudaGetSymbolAddress((void**)&p_xnl,  g_xn_l);
    cudaGetSymbolAddress((void**)&p_ath,  g_at_h);
    cudaGetSymbolAddress((void**)&p_atl,  g_at_l);
    cudaGetSymbolAddress((void**)&p_wqh,  g_wq_h);
    cudaGetSymbolAddress((void**)&p_wql,  g_wq_l);
    cudaGetSymbolAddress((void**)&p_woh,  g_wo_h);
    cudaGetSymbolAddress((void**)&p_wol,  g_wo_l);
    cudaGetSymbolAddress((void**)&p_qh,   g_qh);
    cudaGetSymbolAddress((void**)&p_ql,   g_ql);
    cudaGetSymbolAddress((void**)&p_kh,   g_kh);
    cudaGetSymbolAddress((void**)&p_kl,   g_kl);
    cudaGetSymbolAddress((void**)&p_vh,   g_vh);
    cudaGetSymbolAddress((void**)&p_vl,   g_vl);

    cudaFuncSetAttribute(hgemm_kernel<0>,
                         cudaFuncAttributeMaxDynamicSharedMemorySize, HG_SMEM);
    cudaFuncSetAttribute(hgemm_kernel<1>,
                         cudaFuncAttributeMaxDynamicSharedMemorySize, HG_SMEM);
    cudaFuncSetAttribute(attn_mma_kernel,
                         cudaFuncAttributeMaxDynamicSharedMemorySize, ATT_SMEM);

    // 1. pre-norm -> bf16 hi/lo
    rmsnorm_split_kernel<<<BS, 256>>>(hidden, n1w, p_xnh, p_xnl);

    // weight conversions
    split_kernel<<<(DM*QKV_N/4 + 255)/256, 256>>>(wqkv, p_wqh, p_wql, DM*QKV_N/4);
    split_kernel<<<(DM*DM/4 + 255)/256, 256>>>(w_out, p_woh, p_wol, DM*DM/4);

    // 2. QKV projection + clip (HMMA bfx3)
    {
        dim3 grid(QKV_N/128, BS/128);
        hgemm_kernel<0><<<grid, 256, HG_SMEM>>>(p_xnh, p_xnl, p_wqh, p_wql,
                                                nullptr, p_qkv, BS, QKV_N, DM);
    }

    // 3. RoPE + split to bf16 hi/lo
    rope_kernel<<<BS, 256>>>(p_qkv, posids, rsin, rcos,
                             p_qh, p_ql, p_kh, p_kl, p_vh, p_vl);

    // 4. flash attention (HMMA bfx3)
    {
        dim3 grid(SEQ/64, NH, BATCH);
        attn_mma_kernel<<<grid, 256, ATT_SMEM>>>(p_qh, p_ql, p_kh, p_kl,
                                                 p_vh, p_vl, amask, p_ath, p_atl);
    }

    // 5. out-proj + residual add (HMMA bfx3)
    {
        dim3 grid(DM/128, BS/128);
        hgemm_kernel<1><<<grid, 256, HG_SMEM>>>(p_ath, p_atl, p_woh, p_wol,
                                                hidden, out, BS, DM, DM);
    }

    // 6. post-norm
    rmsnorm_kernel<<<BS, 256>>>(out, n2w, out + (size_t)BS * DM);
}